// round 7
// baseline (speedup 1.0000x reference)
#include <cuda_runtime.h>
#include <cuda_bf16.h>
#include <mma.h>
#include <math.h>
#include <stdint.h>

using namespace nvcuda;

#define BB     16
#define MTOT   256
#define DD     4096
#define HKK    8
#define STARTP 2048
#define TTOT   2064
#define NKV    1024
#define NTILE  33          // ceil(2064/64)
#define PSTRIDE (NTILE*64) // 2112

// f32 scratch
__device__ float g_k[MTOT * NKV];
__device__ float g_v[MTOT * NKV];
__device__ float g_part_o[4 * 128 * 64 * 128];
__device__ float g_sl[NTILE * 128 * 64];

// bf16 hi/lo operands
__device__ __nv_bfloat16 g_xh[MTOT * DD],  g_xl[MTOT * DD];
__device__ __nv_bfloat16 g_qh[128 * 64 * 128], g_ql[128 * 64 * 128];  // [bhk][row][d]
__device__ __nv_bfloat16 g_zh[MTOT * DD],  g_zl[MTOT * DD];
__device__ __nv_bfloat16 g_wqh[DD * DD],   g_wql[DD * DD];
__device__ __nv_bfloat16 g_wkh[DD * NKV],  g_wkl[DD * NKV];
__device__ __nv_bfloat16 g_wvh[DD * NKV],  g_wvl[DD * NKV];
__device__ __nv_bfloat16 g_woh[DD * DD],   g_wol[DD * DD];
__device__ __nv_bfloat16 g_ph[128 * 64 * PSTRIDE], g_pl[128 * 64 * PSTRIDE];

// ---------------------------------------------------------------------------
__device__ __forceinline__ void split2(float a0, float a1,
                                       __nv_bfloat162* h, __nv_bfloat162* l)
{
    __nv_bfloat162 hh = __floats2bfloat162_rn(a0, a1);
    *h = hh;
    *l = __floats2bfloat162_rn(a0 - __low2float(hh), a1 - __high2float(hh));
}

__device__ __forceinline__ void split_store4(float4 v, float s,
                                             __nv_bfloat16* hp, __nv_bfloat16* lp)
{
    __nv_bfloat162 h0, l0, h1, l1;
    split2(v.x * s, v.y * s, &h0, &l0);
    split2(v.z * s, v.w * s, &h1, &l1);
    *(__nv_bfloat162*)(hp)     = h0;
    *(__nv_bfloat162*)(hp + 2) = h1;
    *(__nv_bfloat162*)(lp)     = l0;
    *(__nv_bfloat162*)(lp + 2) = l1;
}

__device__ __forceinline__ void cp16(uint32_t dst_smem, const void* src) {
    asm volatile("cp.async.ca.shared.global [%0], [%1], 16;"
                 :: "r"(dst_smem), "l"(src) : "memory");
}
#define CP_COMMIT() asm volatile("cp.async.commit_group;" ::: "memory")
#define CP_WAIT1()  asm volatile("cp.async.wait_group 1;" ::: "memory")
#define CP_WAIT0()  asm volatile("cp.async.wait_group 0;" ::: "memory")

// ---------------------------------------------------------------------------
// Preconversion: f32 -> bf16 hi/lo
// ---------------------------------------------------------------------------
__global__ __launch_bounds__(256)
void split_kernel(const float* __restrict__ in, __nv_bfloat16* __restrict__ h,
                  __nv_bfloat16* __restrict__ l, int n4)
{
    int i = blockIdx.x * 256 + threadIdx.x;
    if (i >= n4) return;
    float4 v = ((const float4*)in)[i];
    __nv_bfloat162 h0, l0, h1, l1;
    split2(v.x, v.y, &h0, &l0);
    split2(v.z, v.w, &h1, &l1);
    ((__nv_bfloat162*)h)[2 * i]     = h0;
    ((__nv_bfloat162*)h)[2 * i + 1] = h1;
    ((__nv_bfloat162*)l)[2 * i]     = l0;
    ((__nv_bfloat162*)l)[2 * i + 1] = l1;
}

// ---------------------------------------------------------------------------
// GEMM (bf16x3, wmma, cp.async double-buffered): Out[256,Nc] = A @ W
// Tile 64x128, BK=64, 256 threads. dest=0: q (rope+scale+split->g_qh/g_ql),
// dest=1: k (rope, f32), dest=2: v (f32), dest=3: plain f32 (wo -> out).
// ---------------------------------------------------------------------------
#define GA_LD 72
#define GB_LD 136
#define GS_LD 136
#define OFF_AH 0
#define OFF_AL (OFF_AH + 64 * GA_LD * 2)
#define OFF_BH (OFF_AL + 64 * GA_LD * 2)
#define OFF_BL (OFF_BH + 64 * GB_LD * 2)
#define STAGE_BYTES (OFF_BL + 64 * GB_LD * 2)
#define GEMM_SMEM (2 * STAGE_BYTES)

__global__ __launch_bounds__(256)
void gemm_bf16x3(const __nv_bfloat16* __restrict__ Ah, const __nv_bfloat16* __restrict__ Al,
                 const __nv_bfloat16* __restrict__ W0h, const __nv_bfloat16* __restrict__ W0l,
                 const __nv_bfloat16* __restrict__ W1h, const __nv_bfloat16* __restrict__ W1l,
                 const __nv_bfloat16* __restrict__ W2h, const __nv_bfloat16* __restrict__ W2l,
                 float* __restrict__ O1f, float* __restrict__ O2f, float* __restrict__ O3f,
                 const float* __restrict__ fc, const float* __restrict__ fs, int fused)
{
    extern __shared__ char sm[];
    const uint32_t sb = (uint32_t)__cvta_generic_to_shared(sm);

    const int tid = threadIdx.x;
    const int m0  = blockIdx.x * 64;
    const int nt  = blockIdx.y;

    const __nv_bfloat16 *Wh, *Wl; int Nc, dest, n0;
    if (fused) {
        if (nt < 32)      { Wh = W0h; Wl = W0l; Nc = 4096; dest = 0; n0 = nt * 128; }
        else if (nt < 40) { Wh = W1h; Wl = W1l; Nc = 1024; dest = 1; n0 = (nt - 32) * 128; }
        else              { Wh = W2h; Wl = W2l; Nc = 1024; dest = 2; n0 = (nt - 40) * 128; }
    } else {
        Wh = W0h; Wl = W0l; Nc = 4096; dest = 3; n0 = nt * 128;
    }

    const int warp = tid >> 5;
    const int rowg = warp >> 2;
    const int colg = warp & 3;

    const int ar = tid >> 3, ac = (tid & 7) * 8;
    const int br = tid >> 4, bc = (tid & 15) * 8;

    wmma::fragment<wmma::accumulator, 16, 16, 16, float> acc[2][2];
#pragma unroll
    for (int i = 0; i < 2; i++)
#pragma unroll
        for (int j = 0; j < 2; j++) wmma::fill_fragment(acc[i][j], 0.f);

    auto issue_stage = [&](int s, int k0) {
        const uint32_t st = sb + s * STAGE_BYTES;
#pragma unroll
        for (int j = 0; j < 2; j++) {
            const int r = ar + 32 * j;
            const size_t so = (size_t)(m0 + r) * DD + k0 + ac;
            cp16(st + OFF_AH + r * (GA_LD * 2) + ac * 2, Ah + so);
            cp16(st + OFF_AL + r * (GA_LD * 2) + ac * 2, Al + so);
        }
#pragma unroll
        for (int j = 0; j < 4; j++) {
            const int r = br + 16 * j;
            const size_t so = (size_t)(k0 + r) * Nc + n0 + bc;
            cp16(st + OFF_BH + r * (GB_LD * 2) + bc * 2, Wh + so);
            cp16(st + OFF_BL + r * (GB_LD * 2) + bc * 2, Wl + so);
        }
        CP_COMMIT();
    };

    issue_stage(0, 0);

    const int NIT = DD / 64;
    for (int it = 0; it < NIT; it++) {
        if (it + 1 < NIT) { issue_stage((it + 1) & 1, (it + 1) * 64); CP_WAIT1(); }
        else              { CP_WAIT0(); }
        __syncthreads();

        const char* stg = sm + (it & 1) * STAGE_BYTES;
        const __nv_bfloat16* AHs = (const __nv_bfloat16*)(stg + OFF_AH);
        const __nv_bfloat16* ALs = (const __nv_bfloat16*)(stg + OFF_AL);
        const __nv_bfloat16* BHs = (const __nv_bfloat16*)(stg + OFF_BH);
        const __nv_bfloat16* BLs = (const __nv_bfloat16*)(stg + OFF_BL);

#pragma unroll
        for (int kk = 0; kk < 4; kk++) {
            wmma::fragment<wmma::matrix_a, 16, 16, 16, __nv_bfloat16, wmma::row_major> ah[2], al[2];
#pragma unroll
            for (int i = 0; i < 2; i++) {
                wmma::load_matrix_sync(ah[i], AHs + (rowg * 32 + 16 * i) * GA_LD + kk * 16, GA_LD);
                wmma::load_matrix_sync(al[i], ALs + (rowg * 32 + 16 * i) * GA_LD + kk * 16, GA_LD);
            }
#pragma unroll
            for (int j = 0; j < 2; j++) {
                wmma::fragment<wmma::matrix_b, 16, 16, 16, __nv_bfloat16, wmma::row_major> bh, bl;
                wmma::load_matrix_sync(bh, BHs + (kk * 16) * GB_LD + colg * 32 + 16 * j, GB_LD);
                wmma::load_matrix_sync(bl, BLs + (kk * 16) * GB_LD + colg * 32 + 16 * j, GB_LD);
#pragma unroll
                for (int i = 0; i < 2; i++) {
                    wmma::mma_sync(acc[i][j], ah[i], bh, acc[i][j]);
                    wmma::mma_sync(acc[i][j], ah[i], bl, acc[i][j]);
                    wmma::mma_sync(acc[i][j], al[i], bh, acc[i][j]);
                }
            }
        }
        __syncthreads();
    }

    float* SO = (float*)sm;
#pragma unroll
    for (int i = 0; i < 2; i++)
#pragma unroll
        for (int j = 0; j < 2; j++)
            wmma::store_matrix_sync(SO + (rowg * 32 + 16 * i) * GS_LD + colg * 32 + 16 * j,
                                    acc[i][j], GS_LD, wmma::mem_row_major);
    __syncthreads();

    const int erow = tid >> 2;
    const int ec0  = (tid & 3) * 32;
    const int m    = m0 + erow;
    const int tok  = m & 15;
    const float* srow = SO + erow * GS_LD + ec0;

    if (dest == 0) {
        // q: rope + scale + hi/lo split into [bhk][row][d] layout
        const int h   = n0 >> 7;                 // global head (ec0 < 128)
        const int hk  = h >> 2, rep = h & 3;
        const int b   = m >> 4, n = m & 15;
        const size_t qb = ((size_t)(b * 8 + hk) * 64 + rep * 16 + n) * 128 + ec0;
#pragma unroll
        for (int j = 0; j < 32; j += 2) {
            const int p = (ec0 + j) >> 1;
            const float co = __ldg(fc + tok * 64 + p), si = __ldg(fs + tok * 64 + p);
            const float a = srow[j], bb = srow[j + 1];
            const float r0 = a * co - bb * si;
            const float r1 = a * si + bb * co;
            __nv_bfloat162 hh, ll;
            split2(r0 * 0.08838834764831845f, r1 * 0.08838834764831845f, &hh, &ll);
            *(__nv_bfloat162*)(g_qh + qb + j) = hh;
            *(__nv_bfloat162*)(g_ql + qb + j) = ll;
        }
    } else if (dest == 1) {
        float* orow = O1f + (size_t)m * Nc + n0 + ec0;
#pragma unroll
        for (int j = 0; j < 32; j += 2) {
            const int p = ((n0 + ec0 + j) & 127) >> 1;
            const float co = __ldg(fc + tok * 64 + p), si = __ldg(fs + tok * 64 + p);
            const float a = srow[j], bb = srow[j + 1];
            orow[j]     = a * co - bb * si;
            orow[j + 1] = a * si + bb * co;
        }
    } else {
        float* orow = ((dest == 2) ? O2f : O3f) + (size_t)m * Nc + n0 + ec0;
#pragma unroll
        for (int j = 0; j < 32; j += 4)
            *(float4*)(orow + j) = *(const float4*)(srow + j);
    }
}

// ---------------------------------------------------------------------------
// Kernel A: S tile (64 q-rows x 64 keys) -> exp+mask -> P (bf16 hi/lo, global)
// grid (33, 128). smem: QH/QL/KH/KL [64][136] bf16; S reuses QH/QL region.
// ---------------------------------------------------------------------------
#define KA_LD 136
#define KA_ARR (64 * KA_LD * 2)          // 17408 B
#define KA_SMEM (4 * KA_ARR)             // 69632 B

__global__ __launch_bounds__(256)
void attn_s_kernel(const float* __restrict__ cache_k)
{
    extern __shared__ char sm[];
    const uint32_t sb = (uint32_t)__cvta_generic_to_shared(sm);
    __nv_bfloat16* QH = (__nv_bfloat16*)(sm);
    __nv_bfloat16* QL = (__nv_bfloat16*)(sm + KA_ARR);
    __nv_bfloat16* KH = (__nv_bfloat16*)(sm + 2 * KA_ARR);
    __nv_bfloat16* KL = (__nv_bfloat16*)(sm + 3 * KA_ARR);
    float*         S  = (float*)(sm);    // reuse QH/QL after MMA

    const int tile = blockIdx.x;
    const int bhk  = blockIdx.y;
    const int b    = bhk >> 3, hk = bhk & 7;
    const int tid  = threadIdx.x;
    const int warp = tid >> 5;
    const int t0   = tile * 64;
    const int tcnt = min(64, TTOT - t0);

    // Q via cp.async (preconverted bf16)
    {
        const int r = tid >> 2, q4 = (tid & 3) * 32;
        const size_t gq = ((size_t)bhk * 64 + r) * 128 + q4;
#pragma unroll
        for (int jj = 0; jj < 4; jj++) {
            const int off = q4 + 8 * jj;
            cp16(sb + r * (KA_LD * 2) + off * 2,            g_qh + gq + 8 * jj);
            cp16(sb + KA_ARR + r * (KA_LD * 2) + off * 2,   g_ql + gq + 8 * jj);
        }
        CP_COMMIT();
    }

    // K chunk f32 -> hi/lo
#pragma unroll
    for (int i = 0; i < 8; i++) {
        const int idx = tid + 256 * i;
        const int tt = idx >> 5, c4 = (idx & 31) * 4;
        const int t = t0 + tt;
        float4 v = make_float4(0.f, 0.f, 0.f, 0.f);
        if (tt < tcnt) {
            v = (t < STARTP)
              ? *(const float4*)(cache_k + (((size_t)b * HKK + hk) * 4096 + t) * 128 + c4)
              : *(const float4*)(g_k + (size_t)(b * 16 + (t - STARTP)) * NKV + hk * 128 + c4);
        }
        split_store4(v, 1.f, &KH[tt * KA_LD + c4], &KL[tt * KA_LD + c4]);
    }
    CP_WAIT0();
    __syncthreads();

    // S = Q K^T (x3 split). warp: rows 16*(warp>>1), cols 32*(warp&1)+{0,16}
    const int rq = warp >> 1;
    const int cw = warp & 1;
    wmma::fragment<wmma::accumulator, 16, 16, 16, float> sacc[2];
    wmma::fill_fragment(sacc[0], 0.f);
    wmma::fill_fragment(sacc[1], 0.f);
#pragma unroll
    for (int kk = 0; kk < 8; kk++) {
        wmma::fragment<wmma::matrix_a, 16, 16, 16, __nv_bfloat16, wmma::row_major> qh, ql;
        wmma::load_matrix_sync(qh, QH + (rq * 16) * KA_LD + kk * 16, KA_LD);
        wmma::load_matrix_sync(ql, QL + (rq * 16) * KA_LD + kk * 16, KA_LD);
#pragma unroll
        for (int j = 0; j < 2; j++) {
            const int tc = cw * 32 + 16 * j;
            wmma::fragment<wmma::matrix_b, 16, 16, 16, __nv_bfloat16, wmma::col_major> khf, klf;
            wmma::load_matrix_sync(khf, KH + tc * KA_LD + kk * 16, KA_LD);
            wmma::load_matrix_sync(klf, KL + tc * KA_LD + kk * 16, KA_LD);
            wmma::mma_sync(sacc[j], qh, khf, sacc[j]);
            wmma::mma_sync(sacc[j], qh, klf, sacc[j]);
            wmma::mma_sync(sacc[j], ql, khf, sacc[j]);
        }
    }
    __syncthreads();   // all Q/K reads done; safe to overwrite with S
    wmma::store_matrix_sync(S + (rq * 16) * 72 + cw * 32,      sacc[0], 72, wmma::mem_row_major);
    wmma::store_matrix_sync(S + (rq * 16) * 72 + cw * 32 + 16, sacc[1], 72, wmma::mem_row_major);
    __syncthreads();

    // exp + mask + hi/lo split -> global P; per-tile row sums -> g_sl
    {
        const int srow = tid >> 2, sub = tid & 3;
        const int lim = STARTP + (srow & 15);
        const float* Srow = S + srow * 72 + sub * 16;
        const size_t pb = ((size_t)bhk * 64 + srow) * PSTRIDE + t0 + sub * 16;
        float ls = 0.f;
#pragma unroll
        for (int c = 0; c < 16; c += 2) {
            const int col = sub * 16 + c;
            const int t = t0 + col;
            float p0 = 0.f, p1 = 0.f;
            if (col < tcnt && t <= lim)         p0 = __expf(Srow[c]);
            if (col + 1 < tcnt && t + 1 <= lim) p1 = __expf(Srow[c + 1]);
            ls += p0 + p1;
            __nv_bfloat162 h, l;
            split2(p0, p1, &h, &l);
            *(__nv_bfloat162*)(g_ph + pb + c) = h;
            *(__nv_bfloat162*)(g_pl + pb + c) = l;
        }
        ls += __shfl_xor_sync(0xffffffffu, ls, 1);
        ls += __shfl_xor_sync(0xffffffffu, ls, 2);
        if (sub == 0) g_sl[(size_t)tile * 8192 + bhk * 64 + srow] = ls;
    }
}

// ---------------------------------------------------------------------------
// Kernel B: O_part = P @ V over a t-range. grid (4, 128).
// P cp.async double-buffered; V f32 register-prefetched -> hi/lo smem.
// ---------------------------------------------------------------------------
#define KB_PLD 72
#define KB_PARR (64 * KB_PLD * 2)        // 9216
#define KB_VOFF (4 * KB_PARR)            // PH0,PL0,PH1,PL1
#define KB_VARR (64 * KA_LD * 2)         // 17408
#define KB_SMEM (KB_VOFF + 2 * KB_VARR)  // 71680

__global__ __launch_bounds__(256)
void attn_pv_kernel(const float* __restrict__ cache_v)
{
    extern __shared__ char sm[];
    const uint32_t sb = (uint32_t)__cvta_generic_to_shared(sm);
    __nv_bfloat16* VH = (__nv_bfloat16*)(sm + KB_VOFF);
    __nv_bfloat16* VL = (__nv_bfloat16*)(sm + KB_VOFF + KB_VARR);

    const int part = blockIdx.x;
    const int bhk  = blockIdx.y;
    const int b    = bhk >> 3, hk = bhk & 7;
    const int tid  = threadIdx.x;
    const int warp = tid >> 5;

    const int tb = (part == 0) ? 0 : 8 * part + 1;
    const int te = 8 * part + 9;

    const int rw = warp >> 1;   // rows 16*rw
    const int ch = warp & 1;    // cols 64*ch
    wmma::fragment<wmma::accumulator, 16, 16, 16, float> oacc[4];
#pragma unroll
    for (int ct = 0; ct < 4; ct++) wmma::fill_fragment(oacc[ct], 0.f);

    // cp.async P tile `t` into stage s
    auto issue_p = [&](int t, int s) {
        const int r = tid >> 2, q4 = (tid & 3) * 16;   // 16 cols = 2 chunks
        const size_t gp = ((size_t)bhk * 64 + r) * PSTRIDE + t * 64 + q4;
        const uint32_t st = sb + (2 * s) * KB_PARR;
#pragma unroll
        for (int jj = 0; jj < 2; jj++) {
            const int off = q4 + 8 * jj;
            cp16(st + r * (KB_PLD * 2) + off * 2,            g_ph + gp + 8 * jj);
            cp16(st + KB_PARR + r * (KB_PLD * 2) + off * 2,  g_pl + gp + 8 * jj);
        }
        CP_COMMIT();
    };

    auto load_v = [&](int t, float4* reg) {
        const int tcnt = min(64, TTOT - t * 64);
#pragma unroll
        for (int i = 0; i < 8; i++) {
            const int idx = tid + 256 * i;
            const int tt = idx >> 5, c4 = (idx & 31) * 4;
            const int tg = t * 64 + tt;
            float4 v = make_float4(0.f, 0.f, 0.f, 0.f);
            if (tt < tcnt) {
                v = (tg < STARTP)
                  ? *(const float4*)(cache_v + (((size_t)b * HKK + hk) * 4096 + tg) * 128 + c4)
                  : *(const float4*)(g_v + (size_t)(b * 16 + (tg - STARTP)) * NKV + hk * 128 + c4);
            }
            reg[i] = v;
        }
    };

    float4 vreg[8];
    issue_p(tb, 0);
    load_v(tb, vreg);

    for (int t = tb; t < te; t++) {
        const int s = (t - tb) & 1;

        // V regs -> smem (prev MMA finished at loop-end sync)
#pragma unroll
        for (int i = 0; i < 8; i++) {
            const int idx = tid + 256 * i;
            const int tt = idx >> 5, c4 = (idx & 31) * 4;
            split_store4(vreg[i], 1.f, &VH[tt * KA_LD + c4], &VL[tt * KA_LD + c4]);
        }
        if (t + 1 < te) { issue_p(t + 1, s ^ 1); CP_WAIT1(); }
        else            { CP_WAIT0(); }
        __syncthreads();    // V + P(t) visible

        if (t + 1 < te) load_v(t + 1, vreg);

        const __nv_bfloat16* PH = (const __nv_bfloat16*)(sm + (2 * s) * KB_PARR);
        const __nv_bfloat16* PL = PH + 64 * KB_PLD;
#pragma unroll
        for (int kk = 0; kk < 4; kk++) {
            wmma::fragment<wmma::matrix_a, 16, 16, 16, __nv_bfloat16, wmma::row_major> pah, pal;
            wmma::load_matrix_sync(pah, PH + (rw * 16) * KB_PLD + kk * 16, KB_PLD);
            wmma::load_matrix_sync(pal, PL + (rw * 16) * KB_PLD + kk * 16, KB_PLD);
#pragma unroll
            for (int ct = 0; ct < 4; ct++) {
                wmma::fragment<wmma::matrix_b, 16, 16, 16, __nv_bfloat16, wmma::row_major> vh, vl;
                wmma::load_matrix_sync(vh, VH + (kk * 16) * KA_LD + ch * 64 + 16 * ct, KA_LD);
                wmma::load_matrix_sync(vl, VL + (kk * 16) * KA_LD + ch * 64 + 16 * ct, KA_LD);
                wmma::mma_sync(oacc[ct], pah, vh, oacc[ct]);
                wmma::mma_sync(oacc[ct], pah, vl, oacc[ct]);
                wmma::mma_sync(oacc[ct], pal, vh, oacc[ct]);
            }
        }
        __syncthreads();    // MMA done before next V overwrite
    }

    const size_t pbase = (size_t)(part * 128 + bhk) * 64;
#pragma unroll
    for (int ct = 0; ct < 4; ct++)
        wmma::store_matrix_sync(g_part_o + (pbase + rw * 16) * 128 + ch * 64 + 16 * ct,
                                oacc[ct], 128, wmma::mem_row_major);
}

// ---------------------------------------------------------------------------
// Combine: O = (sum parts) / (sum tile row-sums) -> z hi/lo (wo GEMM input)
// ---------------------------------------------------------------------------
__global__ __launch_bounds__(256)
void attn_combine_kernel()
{
    const int by  = blockIdx.x;
    const int b   = by >> 3, hk = by & 7;
    const int tid = threadIdx.x;
    const int row = tid >> 2;
    const int dq  = tid & 3;

    float lsum = 0.f;
    for (int t = 0; t < NTILE; t++)
        lsum += g_sl[(size_t)t * 8192 + by * 64 + row];
    const float inv = 1.f / lsum;

    const int rep = row >> 4, n = row & 15;
    const size_t obase = (size_t)(b * 16 + n) * DD + (hk * 4 + rep) * 128 + dq * 32;

#pragma unroll
    for (int d4 = 0; d4 < 8; d4++) {
        float4 acc = make_float4(0.f, 0.f, 0.f, 0.f);
#pragma unroll
        for (int g = 0; g < 4; g++) {
            const float4 v = *(const float4*)(g_part_o +
                ((size_t)(g * 128 + by) * 64 + row) * 128 + dq * 32 + d4 * 4);
            acc.x += v.x; acc.y += v.y; acc.z += v.z; acc.w += v.w;
        }
        acc.x *= inv; acc.y *= inv; acc.z *= inv; acc.w *= inv;
        split_store4(acc, 1.f, g_zh + obase + d4 * 4, g_zl + obase + d4 * 4);
    }
}

// ---------------------------------------------------------------------------
extern "C" void kernel_launch(void* const* d_in, const int* in_sizes, int n_in,
                              void* d_out, int out_size)
{
    (void)in_sizes; (void)n_in; (void)out_size;
    const float* x  = (const float*)d_in[0];
    const float* fc = (const float*)d_in[1];
    const float* fs = (const float*)d_in[2];
    const float* ck = (const float*)d_in[4];
    const float* cv = (const float*)d_in[5];
    const float* wq = (const float*)d_in[6];
    const float* wk = (const float*)d_in[7];
    const float* wv = (const float*)d_in[8];
    const float* wo = (const float*)d_in[9];
    float* out = (float*)d_out;

    float *pk, *pv;
    cudaGetSymbolAddress((void**)&pk, g_k);
    cudaGetSymbolAddress((void**)&pv, g_v);

    __nv_bfloat16 *xh, *xl, *zh, *zl, *wqh, *wql, *wkh, *wkl, *wvh, *wvl, *woh, *wol;
    cudaGetSymbolAddress((void**)&xh,  g_xh);  cudaGetSymbolAddress((void**)&xl,  g_xl);
    cudaGetSymbolAddress((void**)&zh,  g_zh);  cudaGetSymbolAddress((void**)&zl,  g_zl);
    cudaGetSymbolAddress((void**)&wqh, g_wqh); cudaGetSymbolAddress((void**)&wql, g_wql);
    cudaGetSymbolAddress((void**)&wkh, g_wkh); cudaGetSymbolAddress((void**)&wkl, g_wkl);
    cudaGetSymbolAddress((void**)&wvh, g_wvh); cudaGetSymbolAddress((void**)&wvl, g_wvl);
    cudaGetSymbolAddress((void**)&woh, g_woh); cudaGetSymbolAddress((void**)&wol, g_wol);

    cudaFuncSetAttribute(gemm_bf16x3,
                         cudaFuncAttributeMaxDynamicSharedMemorySize, GEMM_SMEM);
    cudaFuncSetAttribute(attn_s_kernel,
                         cudaFuncAttributeMaxDynamicSharedMemorySize, KA_SMEM);
    cudaFuncSetAttribute(attn_pv_kernel,
                         cudaFuncAttributeMaxDynamicSharedMemorySize, KB_SMEM);

    // Preconversion
    split_kernel<<<(MTOT * DD / 4 + 255) / 256, 256>>>(x,  xh,  xl,  MTOT * DD / 4);
    split_kernel<<<(DD * DD / 4 + 255) / 256, 256>>>(wq, wqh, wql, DD * DD / 4);
    split_kernel<<<(DD * NKV / 4 + 255) / 256, 256>>>(wk, wkh, wkl, DD * NKV / 4);
    split_kernel<<<(DD * NKV / 4 + 255) / 256, 256>>>(wv, wvh, wvl, DD * NKV / 4);
    split_kernel<<<(DD * DD / 4 + 255) / 256, 256>>>(wo, woh, wol, DD * DD / 4);

    // QKV projection (+RoPE; q written as bf16 hi/lo in attention layout)
    gemm_bf16x3<<<dim3(4, 48), 256, GEMM_SMEM>>>(xh, xl, wqh, wql, wkh, wkl, wvh, wvl,
                                                 pk, pv, nullptr, fc, fs, 1);

    // Attention: S+exp -> P, then P@V, then combine
    attn_s_kernel<<<dim3(NTILE, 128), 256, KA_SMEM>>>(ck);
    attn_pv_kernel<<<dim3(4, 128), 256, KB_SMEM>>>(cv);
    attn_combine_kernel<<<128, 256>>>();

    // Output projection
    gemm_bf16x3<<<dim3(4, 32), 256, GEMM_SMEM>>>(zh, zl, woh, wol, nullptr, nullptr,
                                                 nullptr, nullptr,
                                                 nullptr, nullptr, out, fc, fs, 0);
}

// round 8
// speedup vs baseline: 1.0216x; 1.0216x over previous
#include <cuda_runtime.h>
#include <cuda_bf16.h>
#include <mma.h>
#include <math.h>
#include <stdint.h>

using namespace nvcuda;

#define BB     16
#define MTOT   256
#define DD     4096
#define HKK    8
#define STARTP 2048
#define TTOT   2064
#define NKV    1024
#define NTILE  33
#define PSTRIDE (NTILE*64)
#define NPART  8

// f32 scratch
__device__ float g_k[MTOT * NKV];
__device__ float g_v[MTOT * NKV];
__device__ float g_part_o[NPART * 128 * 64 * 128];
__device__ float g_sl[NTILE * 128 * 64];

// bf16 hi/lo operands
__device__ __nv_bfloat16 g_xh[MTOT * DD],  g_xl[MTOT * DD];
__device__ __nv_bfloat16 g_qh[128 * 64 * 128], g_ql[128 * 64 * 128];
__device__ __nv_bfloat16 g_zh[MTOT * DD],  g_zl[MTOT * DD];
__device__ __nv_bfloat16 g_wqh[DD * DD],   g_wql[DD * DD];
__device__ __nv_bfloat16 g_wkh[DD * NKV],  g_wkl[DD * NKV];
__device__ __nv_bfloat16 g_wvh[DD * NKV],  g_wvl[DD * NKV];
__device__ __nv_bfloat16 g_woh[DD * DD],   g_wol[DD * DD];
__device__ __nv_bfloat16 g_ph[128 * 64 * PSTRIDE], g_pl[128 * 64 * PSTRIDE];

// ---------------------------------------------------------------------------
__device__ __forceinline__ void split2(float a0, float a1,
                                       __nv_bfloat162* h, __nv_bfloat162* l)
{
    __nv_bfloat162 hh = __floats2bfloat162_rn(a0, a1);
    *h = hh;
    *l = __floats2bfloat162_rn(a0 - __low2float(hh), a1 - __high2float(hh));
}

__device__ __forceinline__ void split_store4(float4 v, float s,
                                             __nv_bfloat16* hp, __nv_bfloat16* lp)
{
    __nv_bfloat162 h0, l0, h1, l1;
    split2(v.x * s, v.y * s, &h0, &l0);
    split2(v.z * s, v.w * s, &h1, &l1);
    *(__nv_bfloat162*)(hp)     = h0;
    *(__nv_bfloat162*)(hp + 2) = h1;
    *(__nv_bfloat162*)(lp)     = l0;
    *(__nv_bfloat162*)(lp + 2) = l1;
}

__device__ __forceinline__ void cp16(uint32_t dst_smem, const void* src) {
    asm volatile("cp.async.ca.shared.global [%0], [%1], 16;"
                 :: "r"(dst_smem), "l"(src) : "memory");
}
#define CP_COMMIT() asm volatile("cp.async.commit_group;" ::: "memory")
#define CP_WAIT1()  asm volatile("cp.async.wait_group 1;" ::: "memory")
#define CP_WAIT0()  asm volatile("cp.async.wait_group 0;" ::: "memory")

// ---------------------------------------------------------------------------
// Merged preconversion: all five f32->bf16 hi/lo splits in one launch.
// Segments: x(1024), wq(16384), wk(4096), wv(4096), wo(16384) blocks.
// ---------------------------------------------------------------------------
__global__ __launch_bounds__(256)
void split_all_kernel(const float* __restrict__ x,  const float* __restrict__ wq,
                      const float* __restrict__ wk, const float* __restrict__ wv,
                      const float* __restrict__ wo)
{
    const int blk = blockIdx.x;
    const float* in; __nv_bfloat16 *h, *l; int i0;
    if (blk < 1024)        { in = x;  h = g_xh;  l = g_xl;  i0 = blk; }
    else if (blk < 17408)  { in = wq; h = g_wqh; l = g_wql; i0 = blk - 1024; }
    else if (blk < 21504)  { in = wk; h = g_wkh; l = g_wkl; i0 = blk - 17408; }
    else if (blk < 25600)  { in = wv; h = g_wvh; l = g_wvl; i0 = blk - 21504; }
    else                   { in = wo; h = g_woh; l = g_wol; i0 = blk - 25600; }

    const int i = i0 * 256 + threadIdx.x;
    float4 v = ((const float4*)in)[i];
    __nv_bfloat162 h0, l0, h1, l1;
    split2(v.x, v.y, &h0, &l0);
    split2(v.z, v.w, &h1, &l1);
    ((__nv_bfloat162*)h)[2 * i]     = h0;
    ((__nv_bfloat162*)h)[2 * i + 1] = h1;
    ((__nv_bfloat162*)l)[2 * i]     = l0;
    ((__nv_bfloat162*)l)[2 * i + 1] = l1;
}

// ---------------------------------------------------------------------------
// GEMM (bf16x3, wmma, cp.async double-buffered): Out[256,Nc] = A @ W
// ---------------------------------------------------------------------------
#define GA_LD 72
#define GB_LD 136
#define GS_LD 136
#define OFF_AH 0
#define OFF_AL (OFF_AH + 64 * GA_LD * 2)
#define OFF_BH (OFF_AL + 64 * GA_LD * 2)
#define OFF_BL (OFF_BH + 64 * GB_LD * 2)
#define STAGE_BYTES (OFF_BL + 64 * GB_LD * 2)
#define GEMM_SMEM (2 * STAGE_BYTES)

__global__ __launch_bounds__(256)
void gemm_bf16x3(const __nv_bfloat16* __restrict__ Ah, const __nv_bfloat16* __restrict__ Al,
                 const __nv_bfloat16* __restrict__ W0h, const __nv_bfloat16* __restrict__ W0l,
                 const __nv_bfloat16* __restrict__ W1h, const __nv_bfloat16* __restrict__ W1l,
                 const __nv_bfloat16* __restrict__ W2h, const __nv_bfloat16* __restrict__ W2l,
                 float* __restrict__ O1f, float* __restrict__ O2f, float* __restrict__ O3f,
                 const float* __restrict__ fc, const float* __restrict__ fs, int fused)
{
    extern __shared__ char sm[];
    const uint32_t sb = (uint32_t)__cvta_generic_to_shared(sm);

    const int tid = threadIdx.x;
    const int m0  = blockIdx.x * 64;
    const int nt  = blockIdx.y;

    const __nv_bfloat16 *Wh, *Wl; int Nc, dest, n0;
    if (fused) {
        if (nt < 32)      { Wh = W0h; Wl = W0l; Nc = 4096; dest = 0; n0 = nt * 128; }
        else if (nt < 40) { Wh = W1h; Wl = W1l; Nc = 1024; dest = 1; n0 = (nt - 32) * 128; }
        else              { Wh = W2h; Wl = W2l; Nc = 1024; dest = 2; n0 = (nt - 40) * 128; }
    } else {
        Wh = W0h; Wl = W0l; Nc = 4096; dest = 3; n0 = nt * 128;
    }

    const int warp = tid >> 5;
    const int rowg = warp >> 2;
    const int colg = warp & 3;

    const int ar = tid >> 3, ac = (tid & 7) * 8;
    const int br = tid >> 4, bc = (tid & 15) * 8;

    wmma::fragment<wmma::accumulator, 16, 16, 16, float> acc[2][2];
#pragma unroll
    for (int i = 0; i < 2; i++)
#pragma unroll
        for (int j = 0; j < 2; j++) wmma::fill_fragment(acc[i][j], 0.f);

    auto issue_stage = [&](int s, int k0) {
        const uint32_t st = sb + s * STAGE_BYTES;
#pragma unroll
        for (int j = 0; j < 2; j++) {
            const int r = ar + 32 * j;
            const size_t so = (size_t)(m0 + r) * DD + k0 + ac;
            cp16(st + OFF_AH + r * (GA_LD * 2) + ac * 2, Ah + so);
            cp16(st + OFF_AL + r * (GA_LD * 2) + ac * 2, Al + so);
        }
#pragma unroll
        for (int j = 0; j < 4; j++) {
            const int r = br + 16 * j;
            const size_t so = (size_t)(k0 + r) * Nc + n0 + bc;
            cp16(st + OFF_BH + r * (GB_LD * 2) + bc * 2, Wh + so);
            cp16(st + OFF_BL + r * (GB_LD * 2) + bc * 2, Wl + so);
        }
        CP_COMMIT();
    };

    issue_stage(0, 0);

    const int NIT = DD / 64;
    for (int it = 0; it < NIT; it++) {
        if (it + 1 < NIT) { issue_stage((it + 1) & 1, (it + 1) * 64); CP_WAIT1(); }
        else              { CP_WAIT0(); }
        __syncthreads();

        const char* stg = sm + (it & 1) * STAGE_BYTES;
        const __nv_bfloat16* AHs = (const __nv_bfloat16*)(stg + OFF_AH);
        const __nv_bfloat16* ALs = (const __nv_bfloat16*)(stg + OFF_AL);
        const __nv_bfloat16* BHs = (const __nv_bfloat16*)(stg + OFF_BH);
        const __nv_bfloat16* BLs = (const __nv_bfloat16*)(stg + OFF_BL);

#pragma unroll
        for (int kk = 0; kk < 4; kk++) {
            wmma::fragment<wmma::matrix_a, 16, 16, 16, __nv_bfloat16, wmma::row_major> ah[2], al[2];
#pragma unroll
            for (int i = 0; i < 2; i++) {
                wmma::load_matrix_sync(ah[i], AHs + (rowg * 32 + 16 * i) * GA_LD + kk * 16, GA_LD);
                wmma::load_matrix_sync(al[i], ALs + (rowg * 32 + 16 * i) * GA_LD + kk * 16, GA_LD);
            }
#pragma unroll
            for (int j = 0; j < 2; j++) {
                wmma::fragment<wmma::matrix_b, 16, 16, 16, __nv_bfloat16, wmma::row_major> bh, bl;
                wmma::load_matrix_sync(bh, BHs + (kk * 16) * GB_LD + colg * 32 + 16 * j, GB_LD);
                wmma::load_matrix_sync(bl, BLs + (kk * 16) * GB_LD + colg * 32 + 16 * j, GB_LD);
#pragma unroll
                for (int i = 0; i < 2; i++) {
                    wmma::mma_sync(acc[i][j], ah[i], bh, acc[i][j]);
                    wmma::mma_sync(acc[i][j], ah[i], bl, acc[i][j]);
                    wmma::mma_sync(acc[i][j], al[i], bh, acc[i][j]);
                }
            }
        }
        __syncthreads();
    }

    float* SO = (float*)sm;
#pragma unroll
    for (int i = 0; i < 2; i++)
#pragma unroll
        for (int j = 0; j < 2; j++)
            wmma::store_matrix_sync(SO + (rowg * 32 + 16 * i) * GS_LD + colg * 32 + 16 * j,
                                    acc[i][j], GS_LD, wmma::mem_row_major);
    __syncthreads();

    const int erow = tid >> 2;
    const int ec0  = (tid & 3) * 32;
    const int m    = m0 + erow;
    const int tok  = m & 15;
    const float* srow = SO + erow * GS_LD + ec0;

    if (dest == 0) {
        const int h   = n0 >> 7;
        const int hk  = h >> 2, rep = h & 3;
        const int b   = m >> 4, n = m & 15;
        const size_t qb = ((size_t)(b * 8 + hk) * 64 + rep * 16 + n) * 128 + ec0;
#pragma unroll
        for (int j = 0; j < 32; j += 2) {
            const int p = (ec0 + j) >> 1;
            const float co = __ldg(fc + tok * 64 + p), si = __ldg(fs + tok * 64 + p);
            const float a = srow[j], bb = srow[j + 1];
            const float r0 = a * co - bb * si;
            const float r1 = a * si + bb * co;
            __nv_bfloat162 hh, ll;
            split2(r0 * 0.08838834764831845f, r1 * 0.08838834764831845f, &hh, &ll);
            *(__nv_bfloat162*)(g_qh + qb + j) = hh;
            *(__nv_bfloat162*)(g_ql + qb + j) = ll;
        }
    } else if (dest == 1) {
        float* orow = O1f + (size_t)m * Nc + n0 + ec0;
#pragma unroll
        for (int j = 0; j < 32; j += 2) {
            const int p = ((n0 + ec0 + j) & 127) >> 1;
            const float co = __ldg(fc + tok * 64 + p), si = __ldg(fs + tok * 64 + p);
            const float a = srow[j], bb = srow[j + 1];
            orow[j]     = a * co - bb * si;
            orow[j + 1] = a * si + bb * co;
        }
    } else {
        float* orow = ((dest == 2) ? O2f : O3f) + (size_t)m * Nc + n0 + ec0;
#pragma unroll
        for (int j = 0; j < 32; j += 4)
            *(float4*)(orow + j) = *(const float4*)(srow + j);
    }
}

// ---------------------------------------------------------------------------
// Kernel A: S tiles -> exp+mask -> P. grid (9, 128): 4 key-tiles per CTA.
// Q persistent in smem; K register-prefetched (next tile's LDG overlaps MMA).
// ---------------------------------------------------------------------------
#define KA_LD 136
#define SQH 0
#define SQL (SQH + 64 * KA_LD * 2)
#define SKH (SQL + 64 * KA_LD * 2)
#define SKL (SKH + 64 * KA_LD * 2)
#define SSS (SKL + 64 * KA_LD * 2)
#define KA_SMEM (SSS + 64 * 72 * 4)    // 88064 B -> 2 CTAs/SM

__device__ __forceinline__ void load_k_regs(const float* __restrict__ cache,
                                            const float* __restrict__ gnew,
                                            int b, int hk, int t0, int tid, float4* reg)
{
    const int tcnt = min(64, TTOT - t0);
#pragma unroll
    for (int i = 0; i < 8; i++) {
        const int idx = tid + 256 * i;
        const int tt = idx >> 5, c4 = (idx & 31) * 4;
        const int t = t0 + tt;
        float4 v = make_float4(0.f, 0.f, 0.f, 0.f);
        if (tt < tcnt) {
            v = (t < STARTP)
              ? *(const float4*)(cache + (((size_t)b * HKK + hk) * 4096 + t) * 128 + c4)
              : *(const float4*)(gnew + (size_t)(b * 16 + (t - STARTP)) * NKV + hk * 128 + c4);
        }
        reg[i] = v;
    }
}

__global__ __launch_bounds__(256)
void attn_s_kernel(const float* __restrict__ cache_k)
{
    extern __shared__ char sm[];
    const uint32_t sb = (uint32_t)__cvta_generic_to_shared(sm);
    __nv_bfloat16* QH = (__nv_bfloat16*)(sm + SQH);
    __nv_bfloat16* QL = (__nv_bfloat16*)(sm + SQL);
    __nv_bfloat16* KH = (__nv_bfloat16*)(sm + SKH);
    __nv_bfloat16* KL = (__nv_bfloat16*)(sm + SKL);
    float*         S  = (float*)(sm + SSS);

    const int grp  = blockIdx.x;
    const int bhk  = blockIdx.y;
    const int b    = bhk >> 3, hk = bhk & 7;
    const int tid  = threadIdx.x;
    const int warp = tid >> 5;

    const int tile_b = grp * 4;
    const int tile_e = min(tile_b + 4, NTILE);

    // Q via cp.async (preconverted, pre-scaled bf16)
    {
        const int r = tid >> 2, q4 = (tid & 3) * 32;
        const size_t gq = ((size_t)bhk * 64 + r) * 128 + q4;
#pragma unroll
        for (int jj = 0; jj < 4; jj++) {
            const int off = q4 + 8 * jj;
            cp16(sb + SQH + r * (KA_LD * 2) + off * 2, g_qh + gq + 8 * jj);
            cp16(sb + SQL + r * (KA_LD * 2) + off * 2, g_ql + gq + 8 * jj);
        }
        CP_COMMIT();
    }

    float4 kreg[8];
    load_k_regs(cache_k, g_k, b, hk, tile_b * 64, tid, kreg);
    CP_WAIT0();

    const int rq = warp >> 1;
    const int cw = warp & 1;

    for (int tile = tile_b; tile < tile_e; tile++) {
        const int t0 = tile * 64;
        const int tcnt = min(64, TTOT - t0);

        // K regs -> smem hi/lo
#pragma unroll
        for (int i = 0; i < 8; i++) {
            const int idx = tid + 256 * i;
            const int tt = idx >> 5, c4 = (idx & 31) * 4;
            split_store4(kreg[i], 1.f, &KH[tt * KA_LD + c4], &KL[tt * KA_LD + c4]);
        }
        __syncthreads();

        // prefetch next K while MMAs run
        if (tile + 1 < tile_e)
            load_k_regs(cache_k, g_k, b, hk, (tile + 1) * 64, tid, kreg);

        // S = Q K^T (x3)
        wmma::fragment<wmma::accumulator, 16, 16, 16, float> sacc[2];
        wmma::fill_fragment(sacc[0], 0.f);
        wmma::fill_fragment(sacc[1], 0.f);
#pragma unroll
        for (int kk = 0; kk < 8; kk++) {
            wmma::fragment<wmma::matrix_a, 16, 16, 16, __nv_bfloat16, wmma::row_major> qh, ql;
            wmma::load_matrix_sync(qh, QH + (rq * 16) * KA_LD + kk * 16, KA_LD);
            wmma::load_matrix_sync(ql, QL + (rq * 16) * KA_LD + kk * 16, KA_LD);
#pragma unroll
            for (int j = 0; j < 2; j++) {
                const int tc = cw * 32 + 16 * j;
                wmma::fragment<wmma::matrix_b, 16, 16, 16, __nv_bfloat16, wmma::col_major> khf, klf;
                wmma::load_matrix_sync(khf, KH + tc * KA_LD + kk * 16, KA_LD);
                wmma::load_matrix_sync(klf, KL + tc * KA_LD + kk * 16, KA_LD);
                wmma::mma_sync(sacc[j], qh, khf, sacc[j]);
                wmma::mma_sync(sacc[j], qh, klf, sacc[j]);
                wmma::mma_sync(sacc[j], ql, khf, sacc[j]);
            }
        }
        wmma::store_matrix_sync(S + (rq * 16) * 72 + cw * 32,      sacc[0], 72, wmma::mem_row_major);
        wmma::store_matrix_sync(S + (rq * 16) * 72 + cw * 32 + 16, sacc[1], 72, wmma::mem_row_major);
        __syncthreads();

        // exp + mask + hi/lo split -> global P; per-tile row sums
        {
            const int srow = tid >> 2, sub = tid & 3;
            const int lim = STARTP + (srow & 15);
            const float* Srow = S + srow * 72 + sub * 16;
            const size_t pb = ((size_t)bhk * 64 + srow) * PSTRIDE + t0 + sub * 16;
            float ls = 0.f;
#pragma unroll
            for (int c = 0; c < 16; c += 2) {
                const int col = sub * 16 + c;
                const int t = t0 + col;
                float p0 = 0.f, p1 = 0.f;
                if (col < tcnt && t <= lim)         p0 = __expf(Srow[c]);
                if (col + 1 < tcnt && t + 1 <= lim) p1 = __expf(Srow[c + 1]);
                ls += p0 + p1;
                __nv_bfloat162 h, l;
                split2(p0, p1, &h, &l);
                *(__nv_bfloat162*)(g_ph + pb + c) = h;
                *(__nv_bfloat162*)(g_pl + pb + c) = l;
            }
            ls += __shfl_xor_sync(0xffffffffu, ls, 1);
            ls += __shfl_xor_sync(0xffffffffu, ls, 2);
            if (sub == 0) g_sl[(size_t)tile * 8192 + bhk * 64 + srow] = ls;
        }
        // no sync needed: next loop writes KH/KL (disjoint from S), then syncs
    }
}

// ---------------------------------------------------------------------------
// Kernel B: O_part = P @ V over a tile range. grid (NPART, 128).
// ---------------------------------------------------------------------------
#define KB_PLD 72
#define KB_PARR (64 * KB_PLD * 2)
#define KB_VOFF (4 * KB_PARR)
#define KB_VARR (64 * KA_LD * 2)
#define KB_SMEM (KB_VOFF + 2 * KB_VARR)

__global__ __launch_bounds__(256)
void attn_pv_kernel(const float* __restrict__ cache_v)
{
    extern __shared__ char sm[];
    const uint32_t sb = (uint32_t)__cvta_generic_to_shared(sm);
    __nv_bfloat16* VH = (__nv_bfloat16*)(sm + KB_VOFF);
    __nv_bfloat16* VL = (__nv_bfloat16*)(sm + KB_VOFF + KB_VARR);

    const int part = blockIdx.x;
    const int bhk  = blockIdx.y;
    const int b    = bhk >> 3, hk = bhk & 7;
    const int tid  = threadIdx.x;
    const int warp = tid >> 5;

    const int tb = (part == 0) ? 0 : 4 * part + 1;
    const int te = 4 * part + 5;

    const int rw = warp >> 1;
    const int ch = warp & 1;
    wmma::fragment<wmma::accumulator, 16, 16, 16, float> oacc[4];
#pragma unroll
    for (int ct = 0; ct < 4; ct++) wmma::fill_fragment(oacc[ct], 0.f);

    auto issue_p = [&](int t, int s) {
        const int r = tid >> 2, q4 = (tid & 3) * 16;
        const size_t gp = ((size_t)bhk * 64 + r) * PSTRIDE + t * 64 + q4;
        const uint32_t st = sb + (2 * s) * KB_PARR;
#pragma unroll
        for (int jj = 0; jj < 2; jj++) {
            const int off = q4 + 8 * jj;
            cp16(st + r * (KB_PLD * 2) + off * 2,           g_ph + gp + 8 * jj);
            cp16(st + KB_PARR + r * (KB_PLD * 2) + off * 2, g_pl + gp + 8 * jj);
        }
        CP_COMMIT();
    };

    float4 vreg[8];
    issue_p(tb, 0);
    load_k_regs(cache_v, g_v, b, hk, tb * 64, tid, vreg);

    for (int t = tb; t < te; t++) {
        const int s = (t - tb) & 1;

#pragma unroll
        for (int i = 0; i < 8; i++) {
            const int idx = tid + 256 * i;
            const int tt = idx >> 5, c4 = (idx & 31) * 4;
            split_store4(vreg[i], 1.f, &VH[tt * KA_LD + c4], &VL[tt * KA_LD + c4]);
        }
        if (t + 1 < te) { issue_p(t + 1, s ^ 1); CP_WAIT1(); }
        else            { CP_WAIT0(); }
        __syncthreads();

        if (t + 1 < te) load_k_regs(cache_v, g_v, b, hk, (t + 1) * 64, tid, vreg);

        const __nv_bfloat16* PH = (const __nv_bfloat16*)(sm + (2 * s) * KB_PARR);
        const __nv_bfloat16* PL = PH + 64 * KB_PLD;
#pragma unroll
        for (int kk = 0; kk < 4; kk++) {
            wmma::fragment<wmma::matrix_a, 16, 16, 16, __nv_bfloat16, wmma::row_major> pah, pal;
            wmma::load_matrix_sync(pah, PH + (rw * 16) * KB_PLD + kk * 16, KB_PLD);
            wmma::load_matrix_sync(pal, PL + (rw * 16) * KB_PLD + kk * 16, KB_PLD);
#pragma unroll
            for (int ct = 0; ct < 4; ct++) {
                wmma::fragment<wmma::matrix_b, 16, 16, 16, __nv_bfloat16, wmma::row_major> vh, vl;
                wmma::load_matrix_sync(vh, VH + (kk * 16) * KA_LD + ch * 64 + 16 * ct, KA_LD);
                wmma::load_matrix_sync(vl, VL + (kk * 16) * KA_LD + ch * 64 + 16 * ct, KA_LD);
                wmma::mma_sync(oacc[ct], pah, vh, oacc[ct]);
                wmma::mma_sync(oacc[ct], pah, vl, oacc[ct]);
                wmma::mma_sync(oacc[ct], pal, vh, oacc[ct]);
            }
        }
        __syncthreads();
    }

    const size_t pbase = (size_t)(part * 128 + bhk) * 64;
#pragma unroll
    for (int ct = 0; ct < 4; ct++)
        wmma::store_matrix_sync(g_part_o + (pbase + rw * 16) * 128 + ch * 64 + 16 * ct,
                                oacc[ct], 128, wmma::mem_row_major);
}

// ---------------------------------------------------------------------------
// Combine: O = (sum parts) / (sum tile row-sums) -> z hi/lo
// ---------------------------------------------------------------------------
__global__ __launch_bounds__(256)
void attn_combine_kernel()
{
    const int by  = blockIdx.x;
    const int b   = by >> 3, hk = by & 7;
    const int tid = threadIdx.x;
    const int row = tid >> 2;
    const int dq  = tid & 3;

    float lsum = 0.f;
    for (int t = 0; t < NTILE; t++)
        lsum += g_sl[(size_t)t * 8192 + by * 64 + row];
    const float inv = 1.f / lsum;

    const int rep = row >> 4, n = row & 15;
    const size_t obase = (size_t)(b * 16 + n) * DD + (hk * 4 + rep) * 128 + dq * 32;

#pragma unroll
    for (int d4 = 0; d4 < 8; d4++) {
        float4 acc = make_float4(0.f, 0.f, 0.f, 0.f);
#pragma unroll
        for (int g = 0; g < NPART; g++) {
            const float4 v = *(const float4*)(g_part_o +
                ((size_t)(g * 128 + by) * 64 + row) * 128 + dq * 32 + d4 * 4);
            acc.x += v.x; acc.y += v.y; acc.z += v.z; acc.w += v.w;
        }
        acc.x *= inv; acc.y *= inv; acc.z *= inv; acc.w *= inv;
        split_store4(acc, 1.f, g_zh + obase + d4 * 4, g_zl + obase + d4 * 4);
    }
}

// ---------------------------------------------------------------------------
extern "C" void kernel_launch(void* const* d_in, const int* in_sizes, int n_in,
                              void* d_out, int out_size)
{
    (void)in_sizes; (void)n_in; (void)out_size;
    const float* x  = (const float*)d_in[0];
    const float* fc = (const float*)d_in[1];
    const float* fs = (const float*)d_in[2];
    const float* ck = (const float*)d_in[4];
    const float* cv = (const float*)d_in[5];
    const float* wq = (const float*)d_in[6];
    const float* wk = (const float*)d_in[7];
    const float* wv = (const float*)d_in[8];
    const float* wo = (const float*)d_in[9];
    float* out = (float*)d_out;

    float *pk, *pv;
    cudaGetSymbolAddress((void**)&pk, g_k);
    cudaGetSymbolAddress((void**)&pv, g_v);

    __nv_bfloat16 *xh, *xl, *zh, *zl, *wqh, *wql, *wkh, *wkl, *wvh, *wvl, *woh, *wol;
    cudaGetSymbolAddress((void**)&xh,  g_xh);  cudaGetSymbolAddress((void**)&xl,  g_xl);
    cudaGetSymbolAddress((void**)&zh,  g_zh);  cudaGetSymbolAddress((void**)&zl,  g_zl);
    cudaGetSymbolAddress((void**)&wqh, g_wqh); cudaGetSymbolAddress((void**)&wql, g_wql);
    cudaGetSymbolAddress((void**)&wkh, g_wkh); cudaGetSymbolAddress((void**)&wkl, g_wkl);
    cudaGetSymbolAddress((void**)&wvh, g_wvh); cudaGetSymbolAddress((void**)&wvl, g_wvl);
    cudaGetSymbolAddress((void**)&woh, g_woh); cudaGetSymbolAddress((void**)&wol, g_wol);

    cudaFuncSetAttribute(gemm_bf16x3,
                         cudaFuncAttributeMaxDynamicSharedMemorySize, GEMM_SMEM);
    cudaFuncSetAttribute(attn_s_kernel,
                         cudaFuncAttributeMaxDynamicSharedMemorySize, KA_SMEM);
    cudaFuncSetAttribute(attn_pv_kernel,
                         cudaFuncAttributeMaxDynamicSharedMemorySize, KB_SMEM);

    // Merged preconversion (one launch, 41984 blocks)
    split_all_kernel<<<41984, 256>>>(x, wq, wk, wv, wo);

    // QKV projection (+RoPE; q written as bf16 hi/lo in attention layout)
    gemm_bf16x3<<<dim3(4, 48), 256, GEMM_SMEM>>>(xh, xl, wqh, wql, wkh, wkl, wvh, wvl,
                                                 pk, pv, nullptr, fc, fs, 1);

    // Attention: S+exp -> P (4 tiles/CTA), then P@V (8 parts), then combine
    attn_s_kernel<<<dim3(9, 128), 256, KA_SMEM>>>(ck);
    attn_pv_kernel<<<dim3(NPART, 128), 256, KB_SMEM>>>(cv);
    attn_combine_kernel<<<128, 256>>>();

    // Output projection
    gemm_bf16x3<<<dim3(4, 32), 256, GEMM_SMEM>>>(zh, zl, woh, wol, nullptr, nullptr,
                                                 nullptr, nullptr,
                                                 nullptr, nullptr, out, fc, fs, 0);
}

// round 9
// speedup vs baseline: 1.1691x; 1.1444x over previous
#include <cuda_runtime.h>
#include <cuda_bf16.h>
#include <cuda_fp16.h>
#include <mma.h>
#include <math.h>
#include <stdint.h>

using namespace nvcuda;

#define BB     16
#define MTOT   256
#define DD     4096
#define HKK    8
#define STARTP 2048
#define TTOT   2064
#define NKV    1024
#define NTILE  33
#define PSTRIDE (NTILE*64)
#define NPART  8

// f32 scratch
__device__ float g_k[MTOT * NKV];
__device__ float g_v[MTOT * NKV];
__device__ float g_part_o[NPART * 128 * 64 * 128];
__device__ float g_sl[NTILE * 128 * 64];

// bf16 hi/lo operands (precision-critical paths: QKV gemm, S)
__device__ __nv_bfloat16 g_xh[MTOT * DD],  g_xl[MTOT * DD];
__device__ __nv_bfloat16 g_qh[128 * 64 * 128], g_ql[128 * 64 * 128];
__device__ __nv_bfloat16 g_wqh[DD * DD],   g_wql[DD * DD];
__device__ __nv_bfloat16 g_wkh[DD * NKV],  g_wkl[DD * NKV];
__device__ __nv_bfloat16 g_wvh[DD * NKV],  g_wvl[DD * NKV];

// fp16 operands (linear paths: P.V and wo)
__device__ __half g_ph[128 * 64 * PSTRIDE], g_pl[128 * 64 * PSTRIDE];
__device__ __half g_zh[MTOT * DD], g_zl[MTOT * DD];
__device__ __half g_wo16[DD * DD];

// ---------------------------------------------------------------------------
__device__ __forceinline__ void split2(float a0, float a1,
                                       __nv_bfloat162* h, __nv_bfloat162* l)
{
    __nv_bfloat162 hh = __floats2bfloat162_rn(a0, a1);
    *h = hh;
    *l = __floats2bfloat162_rn(a0 - __low2float(hh), a1 - __high2float(hh));
}

__device__ __forceinline__ void split_store4(float4 v, float s,
                                             __nv_bfloat16* hp, __nv_bfloat16* lp)
{
    __nv_bfloat162 h0, l0, h1, l1;
    split2(v.x * s, v.y * s, &h0, &l0);
    split2(v.z * s, v.w * s, &h1, &l1);
    *(__nv_bfloat162*)(hp)     = h0;
    *(__nv_bfloat162*)(hp + 2) = h1;
    *(__nv_bfloat162*)(lp)     = l0;
    *(__nv_bfloat162*)(lp + 2) = l1;
}

__device__ __forceinline__ void split2h(float a0, float a1, __half2* h, __half2* l)
{
    __half2 hh = __floats2half2_rn(a0, a1);
    float2 hf = __half22float2(hh);
    *h = hh;
    *l = __floats2half2_rn(a0 - hf.x, a1 - hf.y);
}

__device__ __forceinline__ void h4_store(float4 v, __half* p)
{
    *(__half2*)(p)     = __floats2half2_rn(v.x, v.y);
    *(__half2*)(p + 2) = __floats2half2_rn(v.z, v.w);
}

__device__ __forceinline__ void cp16(uint32_t dst_smem, const void* src) {
    asm volatile("cp.async.ca.shared.global [%0], [%1], 16;"
                 :: "r"(dst_smem), "l"(src) : "memory");
}
#define CP_COMMIT() asm volatile("cp.async.commit_group;" ::: "memory")
#define CP_WAIT1()  asm volatile("cp.async.wait_group 1;" ::: "memory")
#define CP_WAIT0()  asm volatile("cp.async.wait_group 0;" ::: "memory")

// ---------------------------------------------------------------------------
// Merged preconversion. Segments: x(1024) bf16 h/l, wq(16384), wk(4096),
// wv(4096) bf16 h/l, wo(16384) single fp16.
// ---------------------------------------------------------------------------
__global__ __launch_bounds__(256)
void split_all_kernel(const float* __restrict__ x,  const float* __restrict__ wq,
                      const float* __restrict__ wk, const float* __restrict__ wv,
                      const float* __restrict__ wo)
{
    const int blk = blockIdx.x;
    if (blk >= 25600) {   // wo -> single fp16
        const int i = (blk - 25600) * 256 + threadIdx.x;
        float4 v = ((const float4*)wo)[i];
        ((__half2*)g_wo16)[2 * i]     = __floats2half2_rn(v.x, v.y);
        ((__half2*)g_wo16)[2 * i + 1] = __floats2half2_rn(v.z, v.w);
        return;
    }
    const float* in; __nv_bfloat16 *h, *l; int i0;
    if (blk < 1024)        { in = x;  h = g_xh;  l = g_xl;  i0 = blk; }
    else if (blk < 17408)  { in = wq; h = g_wqh; l = g_wql; i0 = blk - 1024; }
    else if (blk < 21504)  { in = wk; h = g_wkh; l = g_wkl; i0 = blk - 17408; }
    else                   { in = wv; h = g_wvh; l = g_wvl; i0 = blk - 21504; }

    const int i = i0 * 256 + threadIdx.x;
    float4 v = ((const float4*)in)[i];
    __nv_bfloat162 h0, l0, h1, l1;
    split2(v.x, v.y, &h0, &l0);
    split2(v.z, v.w, &h1, &l1);
    ((__nv_bfloat162*)h)[2 * i]     = h0;
    ((__nv_bfloat162*)h)[2 * i + 1] = h1;
    ((__nv_bfloat162*)l)[2 * i]     = l0;
    ((__nv_bfloat162*)l)[2 * i + 1] = l1;
}

// ---------------------------------------------------------------------------
// QKV GEMM (bf16x3, cp.async double-buffered) — unchanged precision.
// ---------------------------------------------------------------------------
#define GA_LD 72
#define GB_LD 136
#define GS_LD 136
#define OFF_AH 0
#define OFF_AL (OFF_AH + 64 * GA_LD * 2)
#define OFF_BH (OFF_AL + 64 * GA_LD * 2)
#define OFF_BL (OFF_BH + 64 * GB_LD * 2)
#define STAGE_BYTES (OFF_BL + 64 * GB_LD * 2)
#define GEMM_SMEM (2 * STAGE_BYTES)

__global__ __launch_bounds__(256)
void gemm_bf16x3(const __nv_bfloat16* __restrict__ Ah, const __nv_bfloat16* __restrict__ Al,
                 const __nv_bfloat16* __restrict__ W0h, const __nv_bfloat16* __restrict__ W0l,
                 const __nv_bfloat16* __restrict__ W1h, const __nv_bfloat16* __restrict__ W1l,
                 const __nv_bfloat16* __restrict__ W2h, const __nv_bfloat16* __restrict__ W2l,
                 float* __restrict__ O1f, float* __restrict__ O2f,
                 const float* __restrict__ fc, const float* __restrict__ fs)
{
    extern __shared__ char sm[];
    const uint32_t sb = (uint32_t)__cvta_generic_to_shared(sm);

    const int tid = threadIdx.x;
    const int m0  = blockIdx.x * 64;
    const int nt  = blockIdx.y;

    const __nv_bfloat16 *Wh, *Wl; int Nc, dest, n0;
    if (nt < 32)      { Wh = W0h; Wl = W0l; Nc = 4096; dest = 0; n0 = nt * 128; }
    else if (nt < 40) { Wh = W1h; Wl = W1l; Nc = 1024; dest = 1; n0 = (nt - 32) * 128; }
    else              { Wh = W2h; Wl = W2l; Nc = 1024; dest = 2; n0 = (nt - 40) * 128; }

    const int warp = tid >> 5;
    const int rowg = warp >> 2;
    const int colg = warp & 3;

    const int ar = tid >> 3, ac = (tid & 7) * 8;
    const int br = tid >> 4, bc = (tid & 15) * 8;

    wmma::fragment<wmma::accumulator, 16, 16, 16, float> acc[2][2];
#pragma unroll
    for (int i = 0; i < 2; i++)
#pragma unroll
        for (int j = 0; j < 2; j++) wmma::fill_fragment(acc[i][j], 0.f);

    auto issue_stage = [&](int s, int k0) {
        const uint32_t st = sb + s * STAGE_BYTES;
#pragma unroll
        for (int j = 0; j < 2; j++) {
            const int r = ar + 32 * j;
            const size_t so = (size_t)(m0 + r) * DD + k0 + ac;
            cp16(st + OFF_AH + r * (GA_LD * 2) + ac * 2, Ah + so);
            cp16(st + OFF_AL + r * (GA_LD * 2) + ac * 2, Al + so);
        }
#pragma unroll
        for (int j = 0; j < 4; j++) {
            const int r = br + 16 * j;
            const size_t so = (size_t)(k0 + r) * Nc + n0 + bc;
            cp16(st + OFF_BH + r * (GB_LD * 2) + bc * 2, Wh + so);
            cp16(st + OFF_BL + r * (GB_LD * 2) + bc * 2, Wl + so);
        }
        CP_COMMIT();
    };

    issue_stage(0, 0);

    const int NIT = DD / 64;
    for (int it = 0; it < NIT; it++) {
        if (it + 1 < NIT) { issue_stage((it + 1) & 1, (it + 1) * 64); CP_WAIT1(); }
        else              { CP_WAIT0(); }
        __syncthreads();

        const char* stg = sm + (it & 1) * STAGE_BYTES;
        const __nv_bfloat16* AHs = (const __nv_bfloat16*)(stg + OFF_AH);
        const __nv_bfloat16* ALs = (const __nv_bfloat16*)(stg + OFF_AL);
        const __nv_bfloat16* BHs = (const __nv_bfloat16*)(stg + OFF_BH);
        const __nv_bfloat16* BLs = (const __nv_bfloat16*)(stg + OFF_BL);

#pragma unroll
        for (int kk = 0; kk < 4; kk++) {
            wmma::fragment<wmma::matrix_a, 16, 16, 16, __nv_bfloat16, wmma::row_major> ah[2], al[2];
#pragma unroll
            for (int i = 0; i < 2; i++) {
                wmma::load_matrix_sync(ah[i], AHs + (rowg * 32 + 16 * i) * GA_LD + kk * 16, GA_LD);
                wmma::load_matrix_sync(al[i], ALs + (rowg * 32 + 16 * i) * GA_LD + kk * 16, GA_LD);
            }
#pragma unroll
            for (int j = 0; j < 2; j++) {
                wmma::fragment<wmma::matrix_b, 16, 16, 16, __nv_bfloat16, wmma::row_major> bh, bl;
                wmma::load_matrix_sync(bh, BHs + (kk * 16) * GB_LD + colg * 32 + 16 * j, GB_LD);
                wmma::load_matrix_sync(bl, BLs + (kk * 16) * GB_LD + colg * 32 + 16 * j, GB_LD);
#pragma unroll
                for (int i = 0; i < 2; i++) {
                    wmma::mma_sync(acc[i][j], ah[i], bh, acc[i][j]);
                    wmma::mma_sync(acc[i][j], ah[i], bl, acc[i][j]);
                    wmma::mma_sync(acc[i][j], al[i], bh, acc[i][j]);
                }
            }
        }
        __syncthreads();
    }

    float* SO = (float*)sm;
#pragma unroll
    for (int i = 0; i < 2; i++)
#pragma unroll
        for (int j = 0; j < 2; j++)
            wmma::store_matrix_sync(SO + (rowg * 32 + 16 * i) * GS_LD + colg * 32 + 16 * j,
                                    acc[i][j], GS_LD, wmma::mem_row_major);
    __syncthreads();

    const int erow = tid >> 2;
    const int ec0  = (tid & 3) * 32;
    const int m    = m0 + erow;
    const int tok  = m & 15;
    const float* srow = SO + erow * GS_LD + ec0;

    if (dest == 0) {
        const int h   = n0 >> 7;
        const int hk  = h >> 2, rep = h & 3;
        const int b   = m >> 4, n = m & 15;
        const size_t qb = ((size_t)(b * 8 + hk) * 64 + rep * 16 + n) * 128 + ec0;
#pragma unroll
        for (int j = 0; j < 32; j += 2) {
            const int p = (ec0 + j) >> 1;
            const float co = __ldg(fc + tok * 64 + p), si = __ldg(fs + tok * 64 + p);
            const float a = srow[j], bb = srow[j + 1];
            const float r0 = a * co - bb * si;
            const float r1 = a * si + bb * co;
            __nv_bfloat162 hh, ll;
            split2(r0 * 0.08838834764831845f, r1 * 0.08838834764831845f, &hh, &ll);
            *(__nv_bfloat162*)(g_qh + qb + j) = hh;
            *(__nv_bfloat162*)(g_ql + qb + j) = ll;
        }
    } else if (dest == 1) {
        float* orow = O1f + (size_t)m * Nc + n0 + ec0;
#pragma unroll
        for (int j = 0; j < 32; j += 2) {
            const int p = ((n0 + ec0 + j) & 127) >> 1;
            const float co = __ldg(fc + tok * 64 + p), si = __ldg(fs + tok * 64 + p);
            const float a = srow[j], bb = srow[j + 1];
            orow[j]     = a * co - bb * si;
            orow[j + 1] = a * si + bb * co;
        }
    } else {
        float* orow = O2f + (size_t)m * Nc + n0 + ec0;
#pragma unroll
        for (int j = 0; j < 32; j += 4)
            *(float4*)(orow + j) = *(const float4*)(srow + j);
    }
}

// ---------------------------------------------------------------------------
// wo GEMM: out[256,4096] = (zh+zl)[fp16 hi/lo] @ wo[fp16 single]. 2 MMAs/step.
// ---------------------------------------------------------------------------
#define WAH 0
#define WAL (WAH + 64 * GA_LD * 2)
#define WB  (WAL + 64 * GA_LD * 2)
#define WSTAGE (WB + 64 * GB_LD * 2)      // 35840
#define WO_SMEM (2 * WSTAGE)              // 71680

__global__ __launch_bounds__(256)
void gemm_wo_fp16(float* __restrict__ out)
{
    extern __shared__ char sm[];
    const uint32_t sb = (uint32_t)__cvta_generic_to_shared(sm);

    const int tid = threadIdx.x;
    const int m0  = blockIdx.x * 64;
    const int n0  = blockIdx.y * 128;

    const int warp = tid >> 5;
    const int rowg = warp >> 2;
    const int colg = warp & 3;

    const int ar = tid >> 3, ac = (tid & 7) * 8;
    const int br = tid >> 4, bc = (tid & 15) * 8;

    wmma::fragment<wmma::accumulator, 16, 16, 16, float> acc[2][2];
#pragma unroll
    for (int i = 0; i < 2; i++)
#pragma unroll
        for (int j = 0; j < 2; j++) wmma::fill_fragment(acc[i][j], 0.f);

    auto issue_stage = [&](int s, int k0) {
        const uint32_t st = sb + s * WSTAGE;
#pragma unroll
        for (int j = 0; j < 2; j++) {
            const int r = ar + 32 * j;
            const size_t so = (size_t)(m0 + r) * DD + k0 + ac;
            cp16(st + WAH + r * (GA_LD * 2) + ac * 2, g_zh + so);
            cp16(st + WAL + r * (GA_LD * 2) + ac * 2, g_zl + so);
        }
#pragma unroll
        for (int j = 0; j < 4; j++) {
            const int r = br + 16 * j;
            const size_t so = (size_t)(k0 + r) * DD + n0 + bc;
            cp16(st + WB + r * (GB_LD * 2) + bc * 2, g_wo16 + so);
        }
        CP_COMMIT();
    };

    issue_stage(0, 0);

    const int NIT = DD / 64;
    for (int it = 0; it < NIT; it++) {
        if (it + 1 < NIT) { issue_stage((it + 1) & 1, (it + 1) * 64); CP_WAIT1(); }
        else              { CP_WAIT0(); }
        __syncthreads();

        const char* stg = sm + (it & 1) * WSTAGE;
        const __half* AHs = (const __half*)(stg + WAH);
        const __half* ALs = (const __half*)(stg + WAL);
        const __half* Bs  = (const __half*)(stg + WB);

#pragma unroll
        for (int kk = 0; kk < 4; kk++) {
            wmma::fragment<wmma::matrix_a, 16, 16, 16, __half, wmma::row_major> ah[2], al[2];
#pragma unroll
            for (int i = 0; i < 2; i++) {
                wmma::load_matrix_sync(ah[i], AHs + (rowg * 32 + 16 * i) * GA_LD + kk * 16, GA_LD);
                wmma::load_matrix_sync(al[i], ALs + (rowg * 32 + 16 * i) * GA_LD + kk * 16, GA_LD);
            }
#pragma unroll
            for (int j = 0; j < 2; j++) {
                wmma::fragment<wmma::matrix_b, 16, 16, 16, __half, wmma::row_major> bf;
                wmma::load_matrix_sync(bf, Bs + (kk * 16) * GB_LD + colg * 32 + 16 * j, GB_LD);
#pragma unroll
                for (int i = 0; i < 2; i++) {
                    wmma::mma_sync(acc[i][j], ah[i], bf, acc[i][j]);
                    wmma::mma_sync(acc[i][j], al[i], bf, acc[i][j]);
                }
            }
        }
        __syncthreads();
    }

    float* SO = (float*)sm;
#pragma unroll
    for (int i = 0; i < 2; i++)
#pragma unroll
        for (int j = 0; j < 2; j++)
            wmma::store_matrix_sync(SO + (rowg * 32 + 16 * i) * GS_LD + colg * 32 + 16 * j,
                                    acc[i][j], GS_LD, wmma::mem_row_major);
    __syncthreads();

    const int erow = tid >> 2;
    const int ec0  = (tid & 3) * 32;
    float* orow = out + (size_t)(m0 + erow) * DD + n0 + ec0;
    const float* srow = SO + erow * GS_LD + ec0;
#pragma unroll
    for (int j = 0; j < 32; j += 4)
        *(float4*)(orow + j) = *(const float4*)(srow + j);
}

// ---------------------------------------------------------------------------
// Kernel A: S tiles -> exp+mask -> P (fp16 hi/lo). 4 key-tiles per CTA.
// ---------------------------------------------------------------------------
#define KA_LD 136
#define SQH 0
#define SQL (SQH + 64 * KA_LD * 2)
#define SKH (SQL + 64 * KA_LD * 2)
#define SKL (SKH + 64 * KA_LD * 2)
#define SSS (SKL + 64 * KA_LD * 2)
#define KA_SMEM (SSS + 64 * 72 * 4)

__device__ __forceinline__ void load_k_regs(const float* __restrict__ cache,
                                            const float* __restrict__ gnew,
                                            int b, int hk, int t0, int tid, float4* reg)
{
    const int tcnt = min(64, TTOT - t0);
#pragma unroll
    for (int i = 0; i < 8; i++) {
        const int idx = tid + 256 * i;
        const int tt = idx >> 5, c4 = (idx & 31) * 4;
        const int t = t0 + tt;
        float4 v = make_float4(0.f, 0.f, 0.f, 0.f);
        if (tt < tcnt) {
            v = (t < STARTP)
              ? *(const float4*)(cache + (((size_t)b * HKK + hk) * 4096 + t) * 128 + c4)
              : *(const float4*)(gnew + (size_t)(b * 16 + (t - STARTP)) * NKV + hk * 128 + c4);
        }
        reg[i] = v;
    }
}

__global__ __launch_bounds__(256)
void attn_s_kernel(const float* __restrict__ cache_k)
{
    extern __shared__ char sm[];
    const uint32_t sb = (uint32_t)__cvta_generic_to_shared(sm);
    __nv_bfloat16* QH = (__nv_bfloat16*)(sm + SQH);
    __nv_bfloat16* QL = (__nv_bfloat16*)(sm + SQL);
    __nv_bfloat16* KH = (__nv_bfloat16*)(sm + SKH);
    __nv_bfloat16* KL = (__nv_bfloat16*)(sm + SKL);
    float*         S  = (float*)(sm + SSS);

    const int grp  = blockIdx.x;
    const int bhk  = blockIdx.y;
    const int b    = bhk >> 3, hk = bhk & 7;
    const int tid  = threadIdx.x;
    const int warp = tid >> 5;

    const int tile_b = grp * 4;
    const int tile_e = min(tile_b + 4, NTILE);

    {
        const int r = tid >> 2, q4 = (tid & 3) * 32;
        const size_t gq = ((size_t)bhk * 64 + r) * 128 + q4;
#pragma unroll
        for (int jj = 0; jj < 4; jj++) {
            const int off = q4 + 8 * jj;
            cp16(sb + SQH + r * (KA_LD * 2) + off * 2, g_qh + gq + 8 * jj);
            cp16(sb + SQL + r * (KA_LD * 2) + off * 2, g_ql + gq + 8 * jj);
        }
        CP_COMMIT();
    }

    float4 kreg[8];
    load_k_regs(cache_k, g_k, b, hk, tile_b * 64, tid, kreg);
    CP_WAIT0();

    const int rq = warp >> 1;
    const int cw = warp & 1;

    for (int tile = tile_b; tile < tile_e; tile++) {
        const int t0 = tile * 64;
        const int tcnt = min(64, TTOT - t0);

#pragma unroll
        for (int i = 0; i < 8; i++) {
            const int idx = tid + 256 * i;
            const int tt = idx >> 5, c4 = (idx & 31) * 4;
            split_store4(kreg[i], 1.f, &KH[tt * KA_LD + c4], &KL[tt * KA_LD + c4]);
        }
        __syncthreads();

        if (tile + 1 < tile_e)
            load_k_regs(cache_k, g_k, b, hk, (tile + 1) * 64, tid, kreg);

        wmma::fragment<wmma::accumulator, 16, 16, 16, float> sacc[2];
        wmma::fill_fragment(sacc[0], 0.f);
        wmma::fill_fragment(sacc[1], 0.f);
#pragma unroll
        for (int kk = 0; kk < 8; kk++) {
            wmma::fragment<wmma::matrix_a, 16, 16, 16, __nv_bfloat16, wmma::row_major> qh, ql;
            wmma::load_matrix_sync(qh, QH + (rq * 16) * KA_LD + kk * 16, KA_LD);
            wmma::load_matrix_sync(ql, QL + (rq * 16) * KA_LD + kk * 16, KA_LD);
#pragma unroll
            for (int j = 0; j < 2; j++) {
                const int tc = cw * 32 + 16 * j;
                wmma::fragment<wmma::matrix_b, 16, 16, 16, __nv_bfloat16, wmma::col_major> khf, klf;
                wmma::load_matrix_sync(khf, KH + tc * KA_LD + kk * 16, KA_LD);
                wmma::load_matrix_sync(klf, KL + tc * KA_LD + kk * 16, KA_LD);
                wmma::mma_sync(sacc[j], qh, khf, sacc[j]);
                wmma::mma_sync(sacc[j], qh, klf, sacc[j]);
                wmma::mma_sync(sacc[j], ql, khf, sacc[j]);
            }
        }
        wmma::store_matrix_sync(S + (rq * 16) * 72 + cw * 32,      sacc[0], 72, wmma::mem_row_major);
        wmma::store_matrix_sync(S + (rq * 16) * 72 + cw * 32 + 16, sacc[1], 72, wmma::mem_row_major);
        __syncthreads();

        {
            const int srow = tid >> 2, sub = tid & 3;
            const int lim = STARTP + (srow & 15);
            const float* Srow = S + srow * 72 + sub * 16;
            const size_t pb = ((size_t)bhk * 64 + srow) * PSTRIDE + t0 + sub * 16;
            float ls = 0.f;
#pragma unroll
            for (int c = 0; c < 16; c += 2) {
                const int col = sub * 16 + c;
                const int t = t0 + col;
                float p0 = 0.f, p1 = 0.f;
                if (col < tcnt && t <= lim)         p0 = __expf(Srow[c]);
                if (col + 1 < tcnt && t + 1 <= lim) p1 = __expf(Srow[c + 1]);
                ls += p0 + p1;
                __half2 h, l;
                split2h(p0, p1, &h, &l);
                *(__half2*)(g_ph + pb + c) = h;
                *(__half2*)(g_pl + pb + c) = l;
            }
            ls += __shfl_xor_sync(0xffffffffu, ls, 1);
            ls += __shfl_xor_sync(0xffffffffu, ls, 2);
            if (sub == 0) g_sl[(size_t)tile * 8192 + bhk * 64 + srow] = ls;
        }
    }
}

// ---------------------------------------------------------------------------
// Kernel B: O_part = P(fp16 hi/lo) @ V(fp16 single). 2 MMAs per step.
// smem: 2 P stages (PH+PL) + single V array = 54272 B -> 4 CTAs/SM.
// ---------------------------------------------------------------------------
#define PB_LD 72
#define PB_ARR (64 * PB_LD * 2)          // 9216
#define VB_OFF (4 * PB_ARR)              // 36864
#define VB_ARR (64 * KA_LD * 2)          // 17408
#define KB_SMEM (VB_OFF + VB_ARR)        // 54272

__global__ __launch_bounds__(256)
void attn_pv_kernel(const float* __restrict__ cache_v)
{
    extern __shared__ char sm[];
    const uint32_t sb = (uint32_t)__cvta_generic_to_shared(sm);
    __half* VH = (__half*)(sm + VB_OFF);

    const int part = blockIdx.x;
    const int bhk  = blockIdx.y;
    const int b    = bhk >> 3, hk = bhk & 7;
    const int tid  = threadIdx.x;
    const int warp = tid >> 5;

    const int tb = (part == 0) ? 0 : 4 * part + 1;
    const int te = 4 * part + 5;

    const int rw = warp >> 1;
    const int ch = warp & 1;
    wmma::fragment<wmma::accumulator, 16, 16, 16, float> oacc[4];
#pragma unroll
    for (int ct = 0; ct < 4; ct++) wmma::fill_fragment(oacc[ct], 0.f);

    auto issue_p = [&](int t, int s) {
        const int r = tid >> 2, q4 = (tid & 3) * 16;
        const size_t gp = ((size_t)bhk * 64 + r) * PSTRIDE + t * 64 + q4;
        const uint32_t st = sb + (2 * s) * PB_ARR;
#pragma unroll
        for (int jj = 0; jj < 2; jj++) {
            const int off = q4 + 8 * jj;
            cp16(st + r * (PB_LD * 2) + off * 2,           g_ph + gp + 8 * jj);
            cp16(st + PB_ARR + r * (PB_LD * 2) + off * 2,  g_pl + gp + 8 * jj);
        }
        CP_COMMIT();
    };

    float4 vreg[8];
    issue_p(tb, 0);
    load_k_regs(cache_v, g_v, b, hk, tb * 64, tid, vreg);

    for (int t = tb; t < te; t++) {
        const int s = (t - tb) & 1;

#pragma unroll
        for (int i = 0; i < 8; i++) {
            const int idx = tid + 256 * i;
            const int tt = idx >> 5, c4 = (idx & 31) * 4;
            h4_store(vreg[i], &VH[tt * KA_LD + c4]);
        }
        if (t + 1 < te) { issue_p(t + 1, s ^ 1); CP_WAIT1(); }
        else            { CP_WAIT0(); }
        __syncthreads();

        if (t + 1 < te) load_k_regs(cache_v, g_v, b, hk, (t + 1) * 64, tid, vreg);

        const __half* PH = (const __half*)(sm + (2 * s) * PB_ARR);
        const __half* PL = PH + 64 * PB_LD;
#pragma unroll
        for (int kk = 0; kk < 4; kk++) {
            wmma::fragment<wmma::matrix_a, 16, 16, 16, __half, wmma::row_major> pah, pal;
            wmma::load_matrix_sync(pah, PH + (rw * 16) * PB_LD + kk * 16, PB_LD);
            wmma::load_matrix_sync(pal, PL + (rw * 16) * PB_LD + kk * 16, PB_LD);
#pragma unroll
            for (int ct = 0; ct < 4; ct++) {
                wmma::fragment<wmma::matrix_b, 16, 16, 16, __half, wmma::row_major> vf;
                wmma::load_matrix_sync(vf, VH + (kk * 16) * KA_LD + ch * 64 + 16 * ct, KA_LD);
                wmma::mma_sync(oacc[ct], pah, vf, oacc[ct]);
                wmma::mma_sync(oacc[ct], pal, vf, oacc[ct]);
            }
        }
        __syncthreads();
    }

    const size_t pbase = (size_t)(part * 128 + bhk) * 64;
#pragma unroll
    for (int ct = 0; ct < 4; ct++)
        wmma::store_matrix_sync(g_part_o + (pbase + rw * 16) * 128 + ch * 64 + 16 * ct,
                                oacc[ct], 128, wmma::mem_row_major);
}

// ---------------------------------------------------------------------------
// Combine -> z (fp16 hi/lo, wo GEMM input)
// ---------------------------------------------------------------------------
__global__ __launch_bounds__(256)
void attn_combine_kernel()
{
    const int by  = blockIdx.x;
    const int b   = by >> 3, hk = by & 7;
    const int tid = threadIdx.x;
    const int row = tid >> 2;
    const int dq  = tid & 3;

    float lsum = 0.f;
    for (int t = 0; t < NTILE; t++)
        lsum += g_sl[(size_t)t * 8192 + by * 64 + row];
    const float inv = 1.f / lsum;

    const int rep = row >> 4, n = row & 15;
    const size_t obase = (size_t)(b * 16 + n) * DD + (hk * 4 + rep) * 128 + dq * 32;

#pragma unroll
    for (int d4 = 0; d4 < 8; d4++) {
        float4 acc = make_float4(0.f, 0.f, 0.f, 0.f);
#pragma unroll
        for (int g = 0; g < NPART; g++) {
            const float4 v = *(const float4*)(g_part_o +
                ((size_t)(g * 128 + by) * 64 + row) * 128 + dq * 32 + d4 * 4);
            acc.x += v.x; acc.y += v.y; acc.z += v.z; acc.w += v.w;
        }
        acc.x *= inv; acc.y *= inv; acc.z *= inv; acc.w *= inv;
        __half2 h0, l0, h1, l1;
        split2h(acc.x, acc.y, &h0, &l0);
        split2h(acc.z, acc.w, &h1, &l1);
        *(__half2*)(g_zh + obase + d4 * 4)     = h0;
        *(__half2*)(g_zh + obase + d4 * 4 + 2) = h1;
        *(__half2*)(g_zl + obase + d4 * 4)     = l0;
        *(__half2*)(g_zl + obase + d4 * 4 + 2) = l1;
    }
}

// ---------------------------------------------------------------------------
extern "C" void kernel_launch(void* const* d_in, const int* in_sizes, int n_in,
                              void* d_out, int out_size)
{
    (void)in_sizes; (void)n_in; (void)out_size;
    const float* x  = (const float*)d_in[0];
    const float* fc = (const float*)d_in[1];
    const float* fs = (const float*)d_in[2];
    const float* ck = (const float*)d_in[4];
    const float* cv = (const float*)d_in[5];
    const float* wq = (const float*)d_in[6];
    const float* wk = (const float*)d_in[7];
    const float* wv = (const float*)d_in[8];
    const float* wo = (const float*)d_in[9];
    float* out = (float*)d_out;

    float *pk, *pv;
    cudaGetSymbolAddress((void**)&pk, g_k);
    cudaGetSymbolAddress((void**)&pv, g_v);

    __nv_bfloat16 *xh, *xl, *wqh, *wql, *wkh, *wkl, *wvh, *wvl;
    cudaGetSymbolAddress((void**)&xh,  g_xh);  cudaGetSymbolAddress((void**)&xl,  g_xl);
    cudaGetSymbolAddress((void**)&wqh, g_wqh); cudaGetSymbolAddress((void**)&wql, g_wql);
    cudaGetSymbolAddress((void**)&wkh, g_wkh); cudaGetSymbolAddress((void**)&wkl, g_wkl);
    cudaGetSymbolAddress((void**)&wvh, g_wvh); cudaGetSymbolAddress((void**)&wvl, g_wvl);

    cudaFuncSetAttribute(gemm_bf16x3,
                         cudaFuncAttributeMaxDynamicSharedMemorySize, GEMM_SMEM);
    cudaFuncSetAttribute(gemm_wo_fp16,
                         cudaFuncAttributeMaxDynamicSharedMemorySize, WO_SMEM);
    cudaFuncSetAttribute(attn_s_kernel,
                         cudaFuncAttributeMaxDynamicSharedMemorySize, KA_SMEM);
    cudaFuncSetAttribute(attn_pv_kernel,
                         cudaFuncAttributeMaxDynamicSharedMemorySize, KB_SMEM);

    // Merged preconversion
    split_all_kernel<<<41984, 256>>>(x, wq, wk, wv, wo);

    // QKV projection (+RoPE; q -> bf16 hi/lo attention layout)
    gemm_bf16x3<<<dim3(4, 48), 256, GEMM_SMEM>>>(xh, xl, wqh, wql, wkh, wkl, wvh, wvl,
                                                 pk, pv, fc, fs);

    // Attention
    attn_s_kernel<<<dim3(9, 128), 256, KA_SMEM>>>(ck);
    attn_pv_kernel<<<dim3(NPART, 128), 256, KB_SMEM>>>(cv);
    attn_combine_kernel<<<128, 256>>>();

    // Output projection (fp16 A hi/lo x fp16 B single)
    gemm_wo_fp16<<<dim3(4, 32), 256, WO_SMEM>>>(out);
}